// round 5
// baseline (speedup 1.0000x reference)
#include <cuda_runtime.h>
#include <cuda_bf16.h>
#include <cstdint>
#include <math.h>

#define BATCH 8
#define EE    16384

// ============================ scratch ============================
__device__ float g_S[4194304];            // [8][512][1024]
__device__ float g_pooled[6291456];       // [8][1024][768]
__device__ float g_hin[6297600];          // [8][1025][768]  row0 = text_vec
__device__ float g_h[2099200];            // [8][1025][256]
__device__ float g_qkv[6297600];          // [8][1025][768]  packed q|k|v
__device__ float g_elog[524288];          // [8][16384][4] cached edge logits
__device__ float g_tpv[25600];
__device__ float g_ET[25600];
__device__ float g_Wc[64000];
__device__ float g_bc[50];
__device__ float g_msum[8192];
__device__ int   g_cnt[8 * 1026];
__device__ int   g_off[8 * 1026];
__device__ int   g_cur[8 * 1026];
__device__ int   g_elist[131072];
// bf16 split weight tables, transposed to [N][K]
__device__ __nv_bfloat16 g_WH[2752512];
__device__ __nv_bfloat16 g_WL[2752512];
#define OFF_W1   0
#define OFF_W2   786432
#define OFF_NTW  1572864
#define OFF_PROJ 2162688
#define OFF_QKV  2359296

// ============================ helpers ============================
__device__ __forceinline__ uint32_t smem_u32(const void* p) {
    uint32_t a;
    asm("{ .reg .u64 t; cvta.to.shared.u64 t, %1; cvt.u32.u64 %0, t; }" : "=r"(a) : "l"(p));
    return a;
}
__device__ __forceinline__ void ldsm_x4(uint32_t (&r)[4], uint32_t addr) {
    asm volatile("ldmatrix.sync.aligned.m8n8.x4.shared.b16 {%0,%1,%2,%3}, [%4];"
                 : "=r"(r[0]), "=r"(r[1]), "=r"(r[2]), "=r"(r[3]) : "r"(addr));
}
__device__ __forceinline__ void mma16816(float* c, const uint32_t* a, uint32_t b0, uint32_t b1) {
    asm volatile("mma.sync.aligned.m16n8k16.row.col.f32.bf16.bf16.f32 "
                 "{%0,%1,%2,%3}, {%4,%5,%6,%7}, {%8,%9}, {%0,%1,%2,%3};"
                 : "+f"(c[0]), "+f"(c[1]), "+f"(c[2]), "+f"(c[3])
                 : "r"(a[0]), "r"(a[1]), "r"(a[2]), "r"(a[3]), "r"(b0), "r"(b1));
}

// ============================ mega_small: fused small jobs ============================
// grid (250, 7); job = blockIdx.y
__global__ void mega_small(const int* __restrict__ sentence,
                           const float* __restrict__ mask,
                           const float* __restrict__ we,
                           const float* __restrict__ type_table,
                           const float* __restrict__ type_proj_w,
                           const float* __restrict__ edge_type_table,
                           const float* __restrict__ gnn_we,
                           const float* __restrict__ cls_w,
                           const float* __restrict__ cls_b,
                           const float* __restrict__ cls2_w,
                           const float* __restrict__ cls2_b,
                           const float* __restrict__ nm) {
    const int job = blockIdx.y;
    const int blk = blockIdx.x;
    const int t = threadIdx.x;
    if (job == 0) {                       // text encoder, 8 blocks
        if (blk >= 8) return;
        int b = blk;
        __shared__ float sred[256];
        __shared__ float sm[256];
        __shared__ int   sidx[256];
        float mval = mask[b * 256 + t];
        sidx[t] = sentence[b * 256 + t];
        sm[t] = mval;
        sred[t] = mval;
        __syncthreads();
        for (int s = 128; s > 0; s >>= 1) { if (t < s) sred[t] += sred[t + s]; __syncthreads(); }
        float denom = sred[0] + 1e-9f;
        float a0 = 0.f, a1 = 0.f, a2 = 0.f;
        for (int l = 0; l < 256; l++) {
            const float* row = we + (long long)sidx[l] * 768;
            float m = sm[l];
            a0 += row[t] * m; a1 += row[256 + t] * m; a2 += row[512 + t] * m;
        }
        float* o = g_hin + (long long)b * 1025 * 768;
        o[t] = a0 / denom; o[256 + t] = a1 / denom; o[512 + t] = a2 / denom;
    } else if (job >= 1 && job <= 3) {    // small matmuls: tpv (100 blk), ET l0/l1 (50 blk)
        const float* A; const float* Bm; float* Cm; int Mv;
        if (job == 1) { A = type_table; Bm = type_proj_w; Cm = g_tpv; Mv = 100; }
        else if (job == 2) { A = edge_type_table; Bm = gnn_we; Cm = g_ET; Mv = 50; }
        else { A = edge_type_table; Bm = gnn_we + 50 * 256; Cm = g_ET + 50 * 256; Mv = 50; }
        int i = blk * 256 + t;
        if (i >= Mv * 256) return;
        int r = i / 256, c = i % 256;
        float s = 0.f;
        for (int kx = 0; kx < 50; kx++) s += A[r * 50 + kx] * Bm[kx * 256 + c];
        Cm[i] = s;
    } else if (job == 4) {                // Wc = cls_w @ cls2_w^T, 250 blocks
        int i = blk * 256 + t;
        if (i >= 1280 * 50) return;
        int r = i / 50, c = i % 50;
        float s = 0.f;
        for (int kx = 0; kx < 768; kx++) s += cls_w[r * 768 + kx] * cls2_w[c * 768 + kx];
        g_Wc[i] = s;
    } else if (job == 5) {                // bc, 1 block
        if (blk > 0 || t >= 50) return;
        float s = cls2_b[t];
        for (int j = 0; j < 768; j++) s += cls_b[j] * cls2_w[t * 768 + j];
        g_bc[t] = s;
    } else {                              // msum, 32 blocks
        int i = blk * 256 + t;
        if (i >= 8192) return;
        const float* m = nm + (long long)i * 8;
        float s = 0.f;
        #pragma unroll
        for (int q = 0; q < 8; q++) s += m[q];
        g_msum[i] = s;
    }
}

// ============================ mega_prep: all weight splits ============================
struct P10 { const float* p[10]; };
__global__ void mega_prep(P10 srcs) {
    const int Ks[10] = {768, 1024, 768, 768, 256, 256, 256, 256, 256, 256};
    const int Ns[10] = {1024, 768, 768, 256, 256, 256, 256, 256, 256, 256};
    const int Os[10] = {OFF_W1, OFF_W2, OFF_NTW, OFF_PROJ,
                        OFF_QKV, OFF_QKV + 65536, OFF_QKV + 131072,
                        OFF_QKV + 196608, OFF_QKV + 262144, OFF_QKV + 327680};
    int j = blockIdx.y;
    int K = Ks[j], N = Ns[j];
    int i = blockIdx.x * 256 + threadIdx.x;
    if (i >= K * N) return;
    int n = i / K, k = i % K;
    float a = srcs.p[j][(long long)k * N + n];
    __nv_bfloat16 h = __float2bfloat16(a);
    g_WH[Os[j] + i] = h;
    g_WL[Os[j] + i] = __float2bfloat16(a - __bfloat162float(h));
}

// ============================ kg pooling ============================
__global__ void poolkg_kernel(const int* __restrict__ nodes,
                              const float* __restrict__ nm,
                              const float* __restrict__ etab) {
    int n = blockIdx.x, b = blockIdx.y, t = threadIdx.x;
    const int* idx = nodes + ((long long)b * 1024 + n) * 8;
    const float* m = nm + ((long long)b * 1024 + n) * 8;
    long long base[8]; float mv[8];
    #pragma unroll
    for (int i = 0; i < 8; i++) { base[i] = (long long)idx[i] * 768; mv[i] = m[i]; }
    float* o = g_pooled + ((long long)b * 1024 + n) * 768;
    for (int e = t; e < 768; e += 256) {
        float s = 0.f;
        #pragma unroll
        for (int i = 0; i < 8; i++) s += etab[base[i] + e] * mv[i];
        o[e] = s;
    }
}

// ============================ split-bf16 HMMA GEMM ============================
// C[b] = A[b] @ W. W pre-transposed + split into Bh/Bl [Nc][Kd] bf16.
// CTA tile 128x128, ktile 32, 8 warps (warp tile 32x64), mma.sync m16n8k16.
// FUSE=1: MLP1 epilogue relu(acc+bias)*mask, reduce groups of 8 rows -> C[node].
#define LDK 40

template<int FUSE>
__global__ __launch_bounds__(256) void gemm_mma(
    const float* __restrict__ A, long long sA,
    const float* __restrict__ gtab, const int* __restrict__ gidx, long long sG,
    const __nv_bfloat16* __restrict__ Bh, const __nv_bfloat16* __restrict__ Bl,
    float* __restrict__ C, long long sC,
    int Mr, int Nc, int Kd,
    const float* __restrict__ bias,
    const float* __restrict__ rowScale, long long sRS,
    const float* __restrict__ addTab, const int* __restrict__ aidx, long long sAI,
    int relu, const float* __restrict__ nmask)
{
    __shared__ __nv_bfloat16 sAh[128 * LDK];
    __shared__ __nv_bfloat16 sAl[128 * LDK];
    __shared__ __nv_bfloat16 sBh[128 * LDK];
    __shared__ __nv_bfloat16 sBl[128 * LDK];

    const int tid = threadIdx.x;
    const int lane = tid & 31;
    const int wid = tid >> 5;
    const int b = blockIdx.z;
    const int nBase = blockIdx.x * 128;
    const int mBase = blockIdx.y * 128;

    const int lrow = tid >> 1;
    const int lkh = (tid & 1) * 16;
    const int arow = mBase + lrow;
    const bool aval = arow < Mr;
    const float* aptr;
    if (gidx) aptr = gtab + (long long)(aval ? gidx[b * sG + arow] : 0) * Kd + lkh;
    else      aptr = A + b * sA + (long long)arow * Kd + lkh;
    const __nv_bfloat16* bhp = Bh + (long long)(nBase + lrow) * Kd + lkh;
    const __nv_bfloat16* blp = Bl + (long long)(nBase + lrow) * Kd + lkh;

    const uint32_t uAh = smem_u32(sAh), uAl = smem_u32(sAl);
    const uint32_t uBh = smem_u32(sBh), uBl = smem_u32(sBl);
    const uint32_t stsOff = (uint32_t)(lrow * LDK + lkh) * 2;

    const int wm = (wid & 3) * 32;
    const int wn = (wid >> 2) * 64;
    float acc[2][8][4];
    #pragma unroll
    for (int mt = 0; mt < 2; mt++)
        #pragma unroll
        for (int nt = 0; nt < 8; nt++)
            #pragma unroll
            for (int q = 0; q < 4; q++) acc[mt][nt][q] = 0.f;

    const uint32_t aRowOff = (uint32_t)((wm + (lane & 15)) * LDK + (lane >> 4) * 8) * 2;
    const uint32_t bRowOff = (uint32_t)((wn + (lane & 7) + (lane >> 4) * 8) * LDK + ((lane >> 3) & 1) * 8) * 2;

    float4 stA[4];
    uint4  stBh[2], stBl[2];
    {
        if (aval) {
            stA[0] = *reinterpret_cast<const float4*>(aptr + 0);
            stA[1] = *reinterpret_cast<const float4*>(aptr + 4);
            stA[2] = *reinterpret_cast<const float4*>(aptr + 8);
            stA[3] = *reinterpret_cast<const float4*>(aptr + 12);
        } else {
            stA[0] = stA[1] = stA[2] = stA[3] = make_float4(0.f, 0.f, 0.f, 0.f);
        }
        stBh[0] = *reinterpret_cast<const uint4*>(bhp);
        stBh[1] = *reinterpret_cast<const uint4*>(bhp + 8);
        stBl[0] = *reinterpret_cast<const uint4*>(blp);
        stBl[1] = *reinterpret_cast<const uint4*>(blp + 8);
    }

    const int nkt = Kd >> 5;
    for (int kt = 0; kt < nkt; kt++) {
        {
            __nv_bfloat16 hh[16], ll[16];
            const float* af = reinterpret_cast<const float*>(stA);
            #pragma unroll
            for (int i = 0; i < 16; i++) {
                float x = af[i];
                __nv_bfloat16 h = __float2bfloat16(x);
                hh[i] = h;
                ll[i] = __float2bfloat16(x - __bfloat162float(h));
            }
            *reinterpret_cast<uint4*>(reinterpret_cast<char*>(sAh) + stsOff) = *reinterpret_cast<uint4*>(&hh[0]);
            *reinterpret_cast<uint4*>(reinterpret_cast<char*>(sAh) + stsOff + 16) = *reinterpret_cast<uint4*>(&hh[8]);
            *reinterpret_cast<uint4*>(reinterpret_cast<char*>(sAl) + stsOff) = *reinterpret_cast<uint4*>(&ll[0]);
            *reinterpret_cast<uint4*>(reinterpret_cast<char*>(sAl) + stsOff + 16) = *reinterpret_cast<uint4*>(&ll[8]);
            *reinterpret_cast<uint4*>(reinterpret_cast<char*>(sBh) + stsOff) = stBh[0];
            *reinterpret_cast<uint4*>(reinterpret_cast<char*>(sBh) + stsOff + 16) = stBh[1];
            *reinterpret_cast<uint4*>(reinterpret_cast<char*>(sBl) + stsOff) = stBl[0];
            *reinterpret_cast<uint4*>(reinterpret_cast<char*>(sBl) + stsOff + 16) = stBl[1];
        }
        __syncthreads();

        if (kt + 1 < nkt) {
            const int k0 = (kt + 1) * 32;
            if (aval) {
                stA[0] = *reinterpret_cast<const float4*>(aptr + k0 + 0);
                stA[1] = *reinterpret_cast<const float4*>(aptr + k0 + 4);
                stA[2] = *reinterpret_cast<const float4*>(aptr + k0 + 8);
                stA[3] = *reinterpret_cast<const float4*>(aptr + k0 + 12);
            }
            stBh[0] = *reinterpret_cast<const uint4*>(bhp + k0);
            stBh[1] = *reinterpret_cast<const uint4*>(bhp + k0 + 8);
            stBl[0] = *reinterpret_cast<const uint4*>(blp + k0);
            stBl[1] = *reinterpret_cast<const uint4*>(blp + k0 + 8);
        }

        #pragma unroll
        for (int ks = 0; ks < 2; ks++) {
            const uint32_t kso = (uint32_t)(ks * 16) * 2;
            uint32_t ah[2][4], al[2][4];
            #pragma unroll
            for (int mt = 0; mt < 2; mt++) {
                uint32_t ao = aRowOff + (uint32_t)(mt * 16 * LDK) * 2 + kso;
                ldsm_x4(ah[mt], uAh + ao);
                ldsm_x4(al[mt], uAl + ao);
            }
            #pragma unroll
            for (int nt4 = 0; nt4 < 4; nt4++) {
                uint32_t bo = bRowOff + (uint32_t)(nt4 * 16 * LDK) * 2 + kso;
                uint32_t bh[4], bl[4];
                ldsm_x4(bh, uBh + bo);
                ldsm_x4(bl, uBl + bo);
                #pragma unroll
                for (int mt = 0; mt < 2; mt++) {
                    #pragma unroll
                    for (int hf = 0; hf < 2; hf++) {
                        float* c = acc[mt][nt4 * 2 + hf];
                        mma16816(c, ah[mt], bh[hf * 2], bh[hf * 2 + 1]);
                        mma16816(c, ah[mt], bl[hf * 2], bl[hf * 2 + 1]);
                        mma16816(c, al[mt], bh[hf * 2], bh[hf * 2 + 1]);
                    }
                }
            }
        }
        __syncthreads();
    }

    if (FUSE == 1) {
        // MLP1: relu(acc + bias) * mask[row], reduce 8 rows (one node) -> C[b][node][col]
        const int mgrp = lane >> 2;
        const int cpair = (lane & 3) * 2;
        #pragma unroll
        for (int mt = 0; mt < 2; mt++) {
            #pragma unroll
            for (int ri = 0; ri < 2; ri++) {
                const int row = mBase + wm + mt * 16 + ri * 8 + mgrp;
                const float m = nmask[(long long)b * 8192 + 4096 + row];
                float vals[16];
                #pragma unroll
                for (int nt = 0; nt < 8; nt++) {
                    const int col = nBase + wn + nt * 8 + cpair;
                    vals[nt * 2 + 0] = fmaxf(acc[mt][nt][ri * 2 + 0] + bias[col], 0.f) * m;
                    vals[nt * 2 + 1] = fmaxf(acc[mt][nt][ri * 2 + 1] + bias[col + 1], 0.f) * m;
                }
                #pragma unroll
                for (int s = 4; s < 32; s <<= 1) {
                    #pragma unroll
                    for (int i = 0; i < 16; i++) vals[i] += __shfl_xor_sync(0xffffffffu, vals[i], s);
                }
                if (mgrp == 0) {
                    const int node = (mBase + wm + mt * 16 + ri * 8) >> 3;
                    float* srow = C + b * sC + (long long)node * Nc + nBase + wn;
                    #pragma unroll
                    for (int nt = 0; nt < 8; nt++) {
                        srow[nt * 8 + cpair] = vals[nt * 2];
                        srow[nt * 8 + cpair + 1] = vals[nt * 2 + 1];
                    }
                }
            }
        }
        return;
    }

    #pragma unroll
    for (int mt = 0; mt < 2; mt++) {
        const int rbase = mBase + wm + mt * 16 + (lane >> 2);
        #pragma unroll
        for (int ri = 0; ri < 2; ri++) {
            const int row = rbase + ri * 8;
            if (row >= Mr) continue;
            float rs = 1.f;
            if (rowScale) rs = rowScale[b * sRS + row];
            const float* addrow = nullptr;
            if (addTab) addrow = addTab + (long long)aidx[b * sAI + row] * Nc;
            float* crow = C + b * sC + (long long)row * Nc;
            #pragma unroll
            for (int nt = 0; nt < 8; nt++) {
                const int col = nBase + wn + nt * 8 + (lane & 3) * 2;
                float v0 = acc[mt][nt][ri * 2 + 0];
                float v1 = acc[mt][nt][ri * 2 + 1];
                if (bias) { v0 += bias[col] * rs; v1 += bias[col + 1] * rs; }
                if (addrow) { v0 += addrow[col]; v1 += addrow[col + 1]; }
                if (relu) { v0 = fmaxf(v0, 0.f); v1 = fmaxf(v1, 0.f); }
                *reinterpret_cast<float2*>(crow + col) = make_float2(v0, v1);
            }
        }
    }
}

// ============================ CSR build ============================
__global__ void zero_cnt() {
    int i = blockIdx.x * blockDim.x + threadIdx.x;
    if (i < 8 * 1026) g_cnt[i] = 0;
}
__global__ void count_kernel(const int* __restrict__ edges) {
    int i = blockIdx.x * blockDim.x + threadIdx.x;
    if (i >= BATCH * EE) return;
    int b = i / EE, e = i % EE;
    int dst = edges[(long long)b * 2 * EE + EE + e];
    atomicAdd(&g_cnt[b * 1026 + dst], 1);
}
__global__ void scan_kernel() {
    int b = threadIdx.x;
    if (b >= 8) return;
    int acc = 0;
    for (int i = 0; i < 1026; i++) {
        g_off[b * 1026 + i] = acc;
        g_cur[b * 1026 + i] = acc;
        if (i < 1025) acc += g_cnt[b * 1026 + i];
    }
}
__global__ void fill_kernel(const int* __restrict__ edges) {
    int i = blockIdx.x * blockDim.x + threadIdx.x;
    if (i >= BATCH * EE) return;
    int b = i / EE, e = i % EE;
    int dst = edges[(long long)b * 2 * EE + EE + e];
    int pos = atomicAdd(&g_cur[b * 1026 + dst], 1);
    g_elist[b * EE + pos] = e;
}

// ============================ fused GNN attention ============================
__device__ __forceinline__ unsigned fenc(float f) {
    unsigned u = __float_as_uint(f);
    return (u & 0x80000000u) ? ~u : (u | 0x80000000u);
}
__device__ __forceinline__ float fdec(unsigned e) {
    return (e & 0x80000000u) ? __uint_as_float(e ^ 0x80000000u) : __uint_as_float(~e);
}

// qkv packed [b][node][768]: q @ +0, k @ +256, v @ +512
__global__ __launch_bounds__(256) void gnn_edge_kernel(
    const float* __restrict__ qkv,
    float* __restrict__ h,
    const int* __restrict__ edges, const int* __restrict__ etyp,
    const float* __restrict__ ET)
{
    const int node = blockIdx.x;
    const int b = blockIdx.y;
    const int tid = threadIdx.x;
    const int lane = tid & 31;
    const int w = tid >> 5;
    __shared__ float qs[256];
    __shared__ unsigned smax[4];
    __shared__ float sden[4];
    __shared__ float sagg[256];
    qs[tid] = qkv[((long long)b * 1025 + node) * 768 + tid];
    sagg[tid] = 0.f;
    if (tid < 4) { smax[tid] = 0u; sden[tid] = 0.f; }
    __syncthreads();
    const int off = g_off[b * 1026 + node];
    const int deg = g_off[b * 1026 + node + 1] - off;
    const int* el = g_elist + b * EE + off;
    const int* srcArr = edges + (long long)b * 2 * EE;

    // pass 1: logits (cached to g_elog) + max
    float lmax[4] = { -1e30f, -1e30f, -1e30f, -1e30f };
    for (int ei = w; ei < deg; ei += 8) {
        int e = el[ei];
        int src = srcArr[e];
        int et = etyp[(long long)b * EE + e];
        const float* kr = qkv + ((long long)b * 1025 + src) * 768 + 256;
        const float* er = ET + et * 256;
        float hc[4] = {0.f, 0.f, 0.f, 0.f};
        #pragma unroll
        for (int i = 0; i < 8; i++) {
            int d = i * 32 + lane;
            hc[i >> 1] += qs[d] * (kr[d] + er[d]);
        }
        #pragma unroll
        for (int s = 16; s > 0; s >>= 1) {
            #pragma unroll
            for (int hh = 0; hh < 4; hh++) hc[hh] += __shfl_xor_sync(0xffffffffu, hc[hh], s);
        }
        #pragma unroll
        for (int hh = 0; hh < 4; hh++) {
            float lg = hc[hh] * 0.125f;
            lmax[hh] = fmaxf(lmax[hh], lg);
            hc[hh] = lg;
        }
        if (lane < 4) g_elog[((long long)b * EE + off + ei) * 4 + lane] = hc[lane];
    }
    if (lane == 0 && deg > 0) {
        #pragma unroll
        for (int hh = 0; hh < 4; hh++) atomicMax(&smax[hh], fenc(lmax[hh]));
    }
    __syncthreads();
    float mx[4];
    #pragma unroll
    for (int hh = 0; hh < 4; hh++) mx[hh] = fdec(smax[hh]);

    // pass 2: exp from cached logits, weighted V aggregation
    float vacc[8] = {0.f, 0.f, 0.f, 0.f, 0.f, 0.f, 0.f, 0.f};
    float wsum[4] = {0.f, 0.f, 0.f, 0.f};
    for (int ei = w; ei < deg; ei += 8) {
        int e = el[ei];
        int src = srcArr[e];
        float4 lg = *reinterpret_cast<const float4*>(&g_elog[((long long)b * EE + off + ei) * 4]);
        float ex[4];
        ex[0] = expf(lg.x - mx[0]);
        ex[1] = expf(lg.y - mx[1]);
        ex[2] = expf(lg.z - mx[2]);
        ex[3] = expf(lg.w - mx[3]);
        const float* vr = qkv + ((long long)b * 1025 + src) * 768 + 512;
        #pragma unroll
        for (int i = 0; i < 8; i++) {
            int d = i * 32 + lane;
            vacc[i] += ex[i >> 1] * vr[d];
        }
        if (lane == 0) {
            #pragma unroll
            for (int hh = 0; hh < 4; hh++) wsum[hh] += ex[hh];
        }
    }
    if (lane == 0 && deg > 0) {
        #pragma unroll
        for (int hh = 0; hh < 4; hh++) atomicAdd(&sden[hh], wsum[hh]);
    }
    #pragma unroll
    for (int i = 0; i < 8; i++) atomicAdd(&sagg[i * 32 + lane], vacc[i]);
    __syncthreads();
    float den = sden[tid >> 6] + 1e-9f;
    const long long rowOff = ((long long)b * 1025 + node) * 256;
    float val = h[rowOff + tid] + sagg[tid] / den;
    h[rowOff + tid] = fmaxf(val, 0.f);
}

// ============================ final classifier ============================
__global__ void out_kernel(float* __restrict__ out) {
    int c = blockIdx.x, b = blockIdx.y, t = threadIdx.x;
    __shared__ float red[256];
    const float* ctx = g_h + (long long)b * 1025 * 256;
    const float* lab = g_h + ((long long)b * 1025 + 1 + c) * 256;
    const float* txt = g_hin + (long long)b * 1025 * 768;
    float s = 0.f;
    for (int kx = t; kx < 1280; kx += 256) {
        float x;
        if (kx < 256) x = ctx[kx];
        else if (kx < 512) x = lab[kx - 256];
        else x = txt[kx - 512];
        s += x * g_Wc[kx * 50 + c];
    }
    red[t] = s;
    __syncthreads();
    for (int st = 128; st > 0; st >>= 1) { if (t < st) red[t] += red[t + st]; __syncthreads(); }
    if (t == 0) out[b * 50 + c] = red[0] + g_bc[c];
}

// ============================ host ============================
static void launch_gtc(const float* A, long long sA,
                       const float* gtab, const int* gidx, long long sG,
                       const __nv_bfloat16* BH, const __nv_bfloat16* BL,
                       float* C, long long sC, int Mr, int Nc, int Kd,
                       const float* bias, const float* rowScale, long long sRS,
                       const float* addTab, const int* aidx, long long sAI, int relu) {
    dim3 grid(Nc / 128, (Mr + 127) / 128, BATCH);
    gemm_mma<0><<<grid, 256>>>(A, sA, gtab, gidx, sG, BH, BL, C, sC, Mr, Nc, Kd,
                               bias, rowScale, sRS, addTab, aidx, sAI, relu, nullptr);
}

extern "C" void kernel_launch(void* const* d_in, const int* in_sizes, int n_in,
                              void* d_out, int out_size) {
    (void)in_sizes; (void)n_in; (void)out_size;
    const int*   sentence        = (const int*)d_in[0];
    const float* mask            = (const float*)d_in[1];
    const int*   nodes           = (const int*)d_in[2];
    const float* node_mask       = (const float*)d_in[3];
    const int*   node_types      = (const int*)d_in[4];
    const int*   edges           = (const int*)d_in[5];
    const int*   edge_types      = (const int*)d_in[6];
    const float* word_embed      = (const float*)d_in[7];
    const float* entity_table    = (const float*)d_in[8];
    const float* type_table      = (const float*)d_in[9];
    const float* mlp_w1          = (const float*)d_in[10];
    const float* mlp_b1          = (const float*)d_in[11];
    const float* mlp_w2          = (const float*)d_in[12];
    const float* mlp_b2          = (const float*)d_in[13];
    const float* ntw_w           = (const float*)d_in[14];
    const float* proj_w          = (const float*)d_in[15];
    const float* proj_b          = (const float*)d_in[16];
    const float* type_proj_w     = (const float*)d_in[17];
    const float* edge_type_table = (const float*)d_in[18];
    const float* gnn_wq          = (const float*)d_in[19];
    const float* gnn_wk          = (const float*)d_in[20];
    const float* gnn_wv          = (const float*)d_in[21];
    const float* gnn_we          = (const float*)d_in[22];
    const float* cls_w           = (const float*)d_in[23];
    const float* cls_b           = (const float*)d_in[24];
    const float* cls2_w          = (const float*)d_in[25];
    const float* cls2_b          = (const float*)d_in[26];
    float* out = (float*)d_out;

    float *pS, *pPool, *pHin, *pH, *pQKV, *pTpv, *pET, *pMsum;
    __nv_bfloat16 *pWH, *pWL;
    cudaGetSymbolAddress((void**)&pS, g_S);
    cudaGetSymbolAddress((void**)&pPool, g_pooled);
    cudaGetSymbolAddress((void**)&pHin, g_hin);
    cudaGetSymbolAddress((void**)&pH, g_h);
    cudaGetSymbolAddress((void**)&pQKV, g_qkv);
    cudaGetSymbolAddress((void**)&pTpv, g_tpv);
    cudaGetSymbolAddress((void**)&pET, g_ET);
    cudaGetSymbolAddress((void**)&pMsum, g_msum);
    cudaGetSymbolAddress((void**)&pWH, g_WH);
    cudaGetSymbolAddress((void**)&pWL, g_WL);

    // fused small jobs: text, tpv, ET x2, Wc, bc, msum
    mega_small<<<dim3(250, 7), 256>>>(sentence, mask, word_embed, type_table, type_proj_w,
                                      edge_type_table, gnn_we, cls_w, cls_b, cls2_w, cls2_b,
                                      node_mask);
    // all weight splits in one launch
    P10 srcs;
    srcs.p[0] = mlp_w1; srcs.p[1] = mlp_w2; srcs.p[2] = ntw_w; srcs.p[3] = proj_w;
    srcs.p[4] = gnn_wq; srcs.p[5] = gnn_wk; srcs.p[6] = gnn_wv;
    srcs.p[7] = gnn_wq + 65536; srcs.p[8] = gnn_wk + 65536; srcs.p[9] = gnn_wv + 65536;
    mega_prep<<<dim3(3072, 10), 256>>>(srcs);
    // kg-half pooling
    poolkg_kernel<<<dim3(512, 8), 256>>>(nodes, node_mask, entity_table);
    // MLP1 fused: S[b][node] = sum_m relu(E[idx]@W1 + b1) * mask
    {
        dim3 grid(1024 / 128, 4096 / 128, BATCH);
        gemm_mma<1><<<grid, 256>>>(nullptr, 0, entity_table, nodes + 4096, 8192,
                                   pWH + OFF_W1, pWL + OFF_W1, pS, 512LL * 1024,
                                   4096, 1024, 768, mlp_b1, nullptr, 0,
                                   nullptr, nullptr, 0, 0, node_mask);
    }
    // MLP2: S @ W2 + b2*msum
    launch_gtc(pS, 512LL * 1024, nullptr, nullptr, 0,
               pWH + OFF_W2, pWL + OFF_W2, pPool + 512 * 768, 1024LL * 768, 512, 768, 1024,
               mlp_b2, pMsum + 512, 1024, nullptr, nullptr, 0, 0);
    // ntw
    launch_gtc(pPool, 1024LL * 768, nullptr, nullptr, 0,
               pWH + OFF_NTW, pWL + OFF_NTW, pHin + 768, 1025LL * 768, 1024, 768, 768,
               nullptr, nullptr, 0, nullptr, nullptr, 0, 0);
    // proj (+ node-type embeds)
    launch_gtc(pHin, 1025LL * 768, nullptr, nullptr, 0,
               pWH + OFF_PROJ, pWL + OFF_PROJ, pH, 1025LL * 256, 1025, 256, 768,
               proj_b, nullptr, 0, pTpv, node_types, 1025, 0);
    // CSR
    zero_cnt<<<(8 * 1026 + 255) / 256, 256>>>();
    count_kernel<<<(BATCH * EE) / 256, 256>>>(edges);
    scan_kernel<<<1, 8>>>();
    fill_kernel<<<(BATCH * EE) / 256, 256>>>(edges);
    // GNN layers: fused qkv gemm (Nc=768) then edge kernel
    for (int l = 0; l < 2; l++) {
        launch_gtc(pH, 1025LL * 256, nullptr, nullptr, 0,
                   pWH + OFF_QKV + l * 196608, pWL + OFF_QKV + l * 196608,
                   pQKV, 1025LL * 768, 1025, 768, 256,
                   nullptr, nullptr, 0, nullptr, nullptr, 0, 0);
        gnn_edge_kernel<<<dim3(1025, 8), 256>>>(pQKV, pH, edges, edge_types,
                                                pET + l * 50 * 256);
    }
    out_kernel<<<dim3(50, 8), 256>>>(out);
}

// round 6
// speedup vs baseline: 1.0074x; 1.0074x over previous
#include <cuda_runtime.h>
#include <cuda_bf16.h>
#include <cstdint>
#include <math.h>

#define BATCH 8
#define EE    16384

// ============================ scratch ============================
// split-bf16 activation buffers
__device__ __nv_bfloat16 g_AH[25165824], g_AL[25165824];   // [8][4096][768] gathered MLP1 A
__device__ __nv_bfloat16 g_SH[4194304],  g_SL[4194304];    // [8][512][1024] S
__device__ __nv_bfloat16 g_PH[6291456],  g_PL[6291456];    // [8][1024][768] pooled
__device__ __nv_bfloat16 g_XH[6297600],  g_XL[6297600];    // [8][1025][768] hin
__device__ __nv_bfloat16 g_HH[2099200],  g_HL[2099200];    // [8][1025][256] h
__device__ float g_h[2099200];            // [8][1025][256] fp32 h (residual + classifier)
__device__ float g_qkv[6297600];          // [8][1025][768] packed q|k|v
__device__ float g_elog[524288];          // [8][16384][4]
__device__ float g_hin[6144];             // [8][768] text vec (classifier)
__device__ float g_tpv[25600];
__device__ float g_ET[25600];
__device__ float g_Wc[64000];
__device__ float g_bc[50];
__device__ float g_msum[8192];
__device__ int   g_cnt[8 * 1026];
__device__ int   g_off[8 * 1026];
__device__ int   g_cur[8 * 1026];
__device__ int   g_elist[131072];
// bf16 split weight tables, transposed to [N][K]
__device__ __nv_bfloat16 g_WH[2752512];
__device__ __nv_bfloat16 g_WL[2752512];
#define OFF_W1   0
#define OFF_W2   786432
#define OFF_NTW  1572864
#define OFF_PROJ 2162688
#define OFF_QKV  2359296

// ============================ helpers ============================
__device__ __forceinline__ uint32_t smem_u32(const void* p) {
    uint32_t a;
    asm("{ .reg .u64 t; cvta.to.shared.u64 t, %1; cvt.u32.u64 %0, t; }" : "=r"(a) : "l"(p));
    return a;
}
__device__ __forceinline__ void ldsm_x4(uint32_t (&r)[4], uint32_t addr) {
    asm volatile("ldmatrix.sync.aligned.m8n8.x4.shared.b16 {%0,%1,%2,%3}, [%4];"
                 : "=r"(r[0]), "=r"(r[1]), "=r"(r[2]), "=r"(r[3]) : "r"(addr));
}
__device__ __forceinline__ void mma16816(float* c, const uint32_t* a, uint32_t b0, uint32_t b1) {
    asm volatile("mma.sync.aligned.m16n8k16.row.col.f32.bf16.bf16.f32 "
                 "{%0,%1,%2,%3}, {%4,%5,%6,%7}, {%8,%9}, {%0,%1,%2,%3};"
                 : "+f"(c[0]), "+f"(c[1]), "+f"(c[2]), "+f"(c[3])
                 : "r"(a[0]), "r"(a[1]), "r"(a[2]), "r"(a[3]), "r"(b0), "r"(b1));
}
__device__ __forceinline__ void cp16(uint32_t dst, const void* src, uint32_t len) {
    asm volatile("cp.async.cg.shared.global [%0], [%1], 16, %2;"
                 :: "r"(dst), "l"(src), "r"(len) : "memory");
}
#define CP_COMMIT() asm volatile("cp.async.commit_group;" ::: "memory")
#define CP_WAIT1()  asm volatile("cp.async.wait_group 1;" ::: "memory")
#define CP_WAIT0()  asm volatile("cp.async.wait_group 0;" ::: "memory")

__device__ __forceinline__ void split_store(__nv_bfloat16* oh, __nv_bfloat16* ol, float v) {
    __nv_bfloat16 h = __float2bfloat16(v);
    *oh = h;
    *ol = __float2bfloat16(v - __bfloat162float(h));
}

// ============================ mega_small: fused small jobs ============================
__global__ void mega_small(const int* __restrict__ sentence,
                           const float* __restrict__ mask,
                           const float* __restrict__ we,
                           const float* __restrict__ type_table,
                           const float* __restrict__ type_proj_w,
                           const float* __restrict__ edge_type_table,
                           const float* __restrict__ gnn_we,
                           const float* __restrict__ cls_w,
                           const float* __restrict__ cls_b,
                           const float* __restrict__ cls2_w,
                           const float* __restrict__ cls2_b,
                           const float* __restrict__ nm) {
    const int job = blockIdx.y;
    const int blk = blockIdx.x;
    const int t = threadIdx.x;
    if (job == 0) {                       // text encoder, 8 blocks
        if (blk >= 8) return;
        int b = blk;
        __shared__ float sred[256];
        __shared__ float sm[256];
        __shared__ int   sidx[256];
        float mval = mask[b * 256 + t];
        sidx[t] = sentence[b * 256 + t];
        sm[t] = mval;
        sred[t] = mval;
        __syncthreads();
        for (int s = 128; s > 0; s >>= 1) { if (t < s) sred[t] += sred[t + s]; __syncthreads(); }
        float denom = sred[0] + 1e-9f;
        float a0 = 0.f, a1 = 0.f, a2 = 0.f;
        for (int l = 0; l < 256; l++) {
            const float* row = we + (long long)sidx[l] * 768;
            float m = sm[l];
            a0 += row[t] * m; a1 += row[256 + t] * m; a2 += row[512 + t] * m;
        }
        a0 /= denom; a1 /= denom; a2 /= denom;
        g_hin[b * 768 + t] = a0;
        g_hin[b * 768 + 256 + t] = a1;
        g_hin[b * 768 + 512 + t] = a2;
        long long x0 = (long long)b * 1025 * 768;
        split_store(&g_XH[x0 + t], &g_XL[x0 + t], a0);
        split_store(&g_XH[x0 + 256 + t], &g_XL[x0 + 256 + t], a1);
        split_store(&g_XH[x0 + 512 + t], &g_XL[x0 + 512 + t], a2);
    } else if (job >= 1 && job <= 3) {
        const float* A; const float* Bm; float* Cm; int Mv;
        if (job == 1) { A = type_table; Bm = type_proj_w; Cm = g_tpv; Mv = 100; }
        else if (job == 2) { A = edge_type_table; Bm = gnn_we; Cm = g_ET; Mv = 50; }
        else { A = edge_type_table; Bm = gnn_we + 50 * 256; Cm = g_ET + 50 * 256; Mv = 50; }
        int i = blk * 256 + t;
        if (i >= Mv * 256) return;
        int r = i / 256, c = i % 256;
        float s = 0.f;
        for (int kx = 0; kx < 50; kx++) s += A[r * 50 + kx] * Bm[kx * 256 + c];
        Cm[i] = s;
    } else if (job == 4) {
        int i = blk * 256 + t;
        if (i >= 1280 * 50) return;
        int r = i / 50, c = i % 50;
        float s = 0.f;
        for (int kx = 0; kx < 768; kx++) s += cls_w[r * 768 + kx] * cls2_w[c * 768 + kx];
        g_Wc[i] = s;
    } else if (job == 5) {
        if (blk > 0 || t >= 50) return;
        float s = cls2_b[t];
        for (int j = 0; j < 768; j++) s += cls_b[j] * cls2_w[t * 768 + j];
        g_bc[t] = s;
    } else {
        int i = blk * 256 + t;
        if (i >= 8192) return;
        const float* m = nm + (long long)i * 8;
        float s = 0.f;
        #pragma unroll
        for (int q = 0; q < 8; q++) s += m[q];
        g_msum[i] = s;
    }
}

// ============================ mega_prep: all weight splits ============================
struct P10 { const float* p[10]; };
__global__ void mega_prep(P10 srcs) {
    const int Ks[10] = {768, 1024, 768, 768, 256, 256, 256, 256, 256, 256};
    const int Ns[10] = {1024, 768, 768, 256, 256, 256, 256, 256, 256, 256};
    const int Os[10] = {OFF_W1, OFF_W2, OFF_NTW, OFF_PROJ,
                        OFF_QKV, OFF_QKV + 65536, OFF_QKV + 131072,
                        OFF_QKV + 196608, OFF_QKV + 262144, OFF_QKV + 327680};
    int j = blockIdx.y;
    int K = Ks[j], N = Ns[j];
    int i = blockIdx.x * 256 + threadIdx.x;
    if (i >= K * N) return;
    int n = i / K, k = i % K;
    float a = srcs.p[j][(long long)k * N + n];
    __nv_bfloat16 h = __float2bfloat16(a);
    g_WH[Os[j] + i] = h;
    g_WL[Os[j] + i] = __float2bfloat16(a - __bfloat162float(h));
}

// ============================ gather + split MLP1 A rows ============================
__global__ void gatherA(const int* __restrict__ nodes, const float* __restrict__ etab) {
    int r = blockIdx.x, b = blockIdx.y, t = threadIdx.x;
    int idx = nodes[((long long)b * 1024 + 512 + (r >> 3)) * 8 + (r & 7)];
    const float* src = etab + (long long)idx * 768;
    long long o = ((long long)b * 4096 + r) * 768;
    for (int e = t; e < 768; e += 256) {
        split_store(&g_AH[o + e], &g_AL[o + e], src[e]);
    }
}

// ============================ kg pooling (split output) ============================
__global__ void poolkg_kernel(const int* __restrict__ nodes,
                              const float* __restrict__ nm,
                              const float* __restrict__ etab) {
    int n = blockIdx.x, b = blockIdx.y, t = threadIdx.x;
    const int* idx = nodes + ((long long)b * 1024 + n) * 8;
    const float* m = nm + ((long long)b * 1024 + n) * 8;
    long long base[8]; float mv[8];
    #pragma unroll
    for (int i = 0; i < 8; i++) { base[i] = (long long)idx[i] * 768; mv[i] = m[i]; }
    long long o = ((long long)b * 1024 + n) * 768;
    for (int e = t; e < 768; e += 256) {
        float s = 0.f;
        #pragma unroll
        for (int i = 0; i < 8; i++) s += etab[base[i] + e] * mv[i];
        split_store(&g_PH[o + e], &g_PL[o + e], s);
    }
}

// ============================ split-bf16 HMMA GEMM, cp.async double-buffered ============================
#define LDK 40
#define TILE_B 10240u          // 128*40*2 bytes
#define STAGE_B 40960u         // 4 tiles
#define GSMEM 81920            // 2 stages

template<int FUSE>
__global__ __launch_bounds__(256, 2) void gemm_mma(
    const __nv_bfloat16* __restrict__ Ah, const __nv_bfloat16* __restrict__ Al, long long sA,
    const __nv_bfloat16* __restrict__ Bh, const __nv_bfloat16* __restrict__ Bl,
    float* __restrict__ C, long long sC,
    __nv_bfloat16* __restrict__ Ch, __nv_bfloat16* __restrict__ Cl, long long sCb,
    int Mr, int Nc, int Kd,
    const float* __restrict__ bias,
    const float* __restrict__ rowScale, long long sRS,
    const float* __restrict__ addTab, const int* __restrict__ aidx, long long sAI,
    int relu, const float* __restrict__ nmask)
{
    extern __shared__ char dsm[];
    const uint32_t sb = smem_u32(dsm);
    const int tid = threadIdx.x;
    const int lane = tid & 31;
    const int wid = tid >> 5;
    const int b = blockIdx.z;
    const int nBase = blockIdx.x * 128;
    const int mBase = blockIdx.y * 128;

    // loader: thread t -> row = t>>1, half = (t&1)*16 elements
    const int lrow = tid >> 1;
    const int lhalf = (tid & 1) * 16;
    const uint32_t dstoff = (uint32_t)(lrow * 80 + (tid & 1) * 32);
    const int arow = mBase + lrow;
    const uint32_t alen = (arow < Mr) ? 16u : 0u;
    const int arc = arow < Mr ? arow : (Mr - 1);
    const __nv_bfloat16* gAh = Ah + (long long)b * sA + (long long)arc * Kd + lhalf;
    const __nv_bfloat16* gAl = Al + (long long)b * sA + (long long)arc * Kd + lhalf;
    const __nv_bfloat16* gBh = Bh + (long long)(nBase + lrow) * Kd + lhalf;
    const __nv_bfloat16* gBl = Bl + (long long)(nBase + lrow) * Kd + lhalf;

    const int wm = (wid & 3) * 32;
    const int wn = (wid >> 2) * 64;
    float acc[2][8][4];
    #pragma unroll
    for (int mt = 0; mt < 2; mt++)
        #pragma unroll
        for (int nt = 0; nt < 8; nt++)
            #pragma unroll
            for (int q = 0; q < 4; q++) acc[mt][nt][q] = 0.f;

    const uint32_t aRowOff = (uint32_t)((wm + (lane & 15)) * LDK + (lane >> 4) * 8) * 2;
    const uint32_t bRowOff = (uint32_t)((wn + (lane & 7) + (lane >> 4) * 8) * LDK + ((lane >> 3) & 1) * 8) * 2;

    const int nkt = Kd >> 5;
    // prologue: stage 0
    {
        uint32_t s0 = sb;
        cp16(s0 + dstoff, gAh, alen);
        cp16(s0 + dstoff + 16, gAh + 8, alen);
        cp16(s0 + TILE_B + dstoff, gAl, alen);
        cp16(s0 + TILE_B + dstoff + 16, gAl + 8, alen);
        cp16(s0 + 2 * TILE_B + dstoff, gBh, 16);
        cp16(s0 + 2 * TILE_B + dstoff + 16, gBh + 8, 16);
        cp16(s0 + 3 * TILE_B + dstoff, gBl, 16);
        cp16(s0 + 3 * TILE_B + dstoff + 16, gBl + 8, 16);
        CP_COMMIT();
    }

    for (int kt = 0; kt < nkt; kt++) {
        if (kt + 1 < nkt) {
            const int k0 = (kt + 1) * 32;
            uint32_t s1 = sb + ((kt + 1) & 1) * STAGE_B;
            cp16(s1 + dstoff, gAh + k0, alen);
            cp16(s1 + dstoff + 16, gAh + k0 + 8, alen);
            cp16(s1 + TILE_B + dstoff, gAl + k0, alen);
            cp16(s1 + TILE_B + dstoff + 16, gAl + k0 + 8, alen);
            cp16(s1 + 2 * TILE_B + dstoff, gBh + k0, 16);
            cp16(s1 + 2 * TILE_B + dstoff + 16, gBh + k0 + 8, 16);
            cp16(s1 + 3 * TILE_B + dstoff, gBl + k0, 16);
            cp16(s1 + 3 * TILE_B + dstoff + 16, gBl + k0 + 8, 16);
            CP_COMMIT();
            CP_WAIT1();
        } else {
            CP_WAIT0();
        }
        __syncthreads();

        const uint32_t s0 = sb + (kt & 1) * STAGE_B;
        const uint32_t uAh = s0, uAl = s0 + TILE_B;
        const uint32_t uBh = s0 + 2 * TILE_B, uBl = s0 + 3 * TILE_B;
        #pragma unroll
        for (int ks = 0; ks < 2; ks++) {
            const uint32_t kso = (uint32_t)(ks * 16) * 2;
            uint32_t ah[2][4], al[2][4];
            #pragma unroll
            for (int mt = 0; mt < 2; mt++) {
                uint32_t ao = aRowOff + (uint32_t)(mt * 16 * LDK) * 2 + kso;
                ldsm_x4(ah[mt], uAh + ao);
                ldsm_x4(al[mt], uAl + ao);
            }
            #pragma unroll
            for (int nt4 = 0; nt4 < 4; nt4++) {
                uint32_t bo = bRowOff + (uint32_t)(nt4 * 16 * LDK) * 2 + kso;
                uint32_t bh[4], bl[4];
                ldsm_x4(bh, uBh + bo);
                ldsm_x4(bl, uBl + bo);
                #pragma unroll
                for (int mt = 0; mt < 2; mt++) {
                    #pragma unroll
                    for (int hf = 0; hf < 2; hf++) {
                        float* c = acc[mt][nt4 * 2 + hf];
                        mma16816(c, ah[mt], bh[hf * 2], bh[hf * 2 + 1]);
                        mma16816(c, ah[mt], bl[hf * 2], bl[hf * 2 + 1]);
                        mma16816(c, al[mt], bh[hf * 2], bh[hf * 2 + 1]);
                    }
                }
            }
        }
        __syncthreads();
    }

    if (FUSE == 1) {
        // relu(acc + bias) * mask[row]; reduce 8 rows (one node); write split bf16 C
        const int mgrp = lane >> 2;
        const int cpair = (lane & 3) * 2;
        #pragma unroll
        for (int mt = 0; mt < 2; mt++) {
            #pragma unroll
            for (int ri = 0; ri < 2; ri++) {
                const int row = mBase + wm + mt * 16 + ri * 8 + mgrp;
                const float m = nmask[(long long)b * 8192 + 4096 + row];
                float vals[16];
                #pragma unroll
                for (int nt = 0; nt < 8; nt++) {
                    const int col = nBase + wn + nt * 8 + cpair;
                    vals[nt * 2 + 0] = fmaxf(acc[mt][nt][ri * 2 + 0] + bias[col], 0.f) * m;
                    vals[nt * 2 + 1] = fmaxf(acc[mt][nt][ri * 2 + 1] + bias[col + 1], 0.f) * m;
                }
                #pragma unroll
                for (int s = 4; s < 32; s <<= 1) {
                    #pragma unroll
                    for (int i = 0; i < 16; i++) vals[i] += __shfl_xor_sync(0xffffffffu, vals[i], s);
                }
                if (mgrp == 0) {
                    const int node = (mBase + wm + mt * 16 + ri * 8) >> 3;
                    long long o = b * sCb + (long long)node * Nc + nBase + wn;
                    #pragma unroll
                    for (int nt = 0; nt < 8; nt++) {
                        split_store(&Ch[o + nt * 8 + cpair], &Cl[o + nt * 8 + cpair], vals[nt * 2]);
                        split_store(&Ch[o + nt * 8 + cpair + 1], &Cl[o + nt * 8 + cpair + 1], vals[nt * 2 + 1]);
                    }
                }
            }
        }
        return;
    }

    #pragma unroll
    for (int mt = 0; mt < 2; mt++) {
        const int rbase = mBase + wm + mt * 16 + (lane >> 2);
        #pragma unroll
        for (int ri = 0; ri < 2; ri++) {
            const int row = rbase + ri * 8;
            if (row >= Mr) continue;
            float rs = 1.f;
            if (rowScale) rs = rowScale[b * sRS + row];
            const float* addrow = nullptr;
            if (addTab) addrow = addTab + (long long)aidx[b * sAI + row] * Nc;
            float* crow = C ? (C + b * sC + (long long)row * Nc) : nullptr;
            long long ob = Ch ? (b * sCb + (long long)row * Nc) : 0;
            #pragma unroll
            for (int nt = 0; nt < 8; nt++) {
                const int col = nBase + wn + nt * 8 + (lane & 3) * 2;
                float v0 = acc[mt][nt][ri * 2 + 0];
                float v1 = acc[mt][nt][ri * 2 + 1];
                if (bias) { v0 += bias[col] * rs; v1 += bias[col + 1] * rs; }
                if (addrow) { v0 += addrow[col]; v1 += addrow[col + 1]; }
                if (relu) { v0 = fmaxf(v0, 0.f); v1 = fmaxf(v1, 0.f); }
                if (crow) *reinterpret_cast<float2*>(crow + col) = make_float2(v0, v1);
                if (Ch) {
                    split_store(&Ch[ob + col], &Cl[ob + col], v0);
                    split_store(&Ch[ob + col + 1], &Cl[ob + col + 1], v1);
                }
            }
        }
    }
}

// ============================ CSR build ============================
__global__ void zero_cnt() {
    int i = blockIdx.x * blockDim.x + threadIdx.x;
    if (i < 8 * 1026) g_cnt[i] = 0;
}
__global__ void count_kernel(const int* __restrict__ edges) {
    int i = blockIdx.x * blockDim.x + threadIdx.x;
    if (i >= BATCH * EE) return;
    int b = i / EE, e = i % EE;
    int dst = edges[(long long)b * 2 * EE + EE + e];
    atomicAdd(&g_cnt[b * 1026 + dst], 1);
}
__global__ void scan_kernel() {
    int b = threadIdx.x;
    if (b >= 8) return;
    int acc = 0;
    for (int i = 0; i < 1026; i++) {
        g_off[b * 1026 + i] = acc;
        g_cur[b * 1026 + i] = acc;
        if (i < 1025) acc += g_cnt[b * 1026 + i];
    }
}
__global__ void fill_kernel(const int* __restrict__ edges) {
    int i = blockIdx.x * blockDim.x + threadIdx.x;
    if (i >= BATCH * EE) return;
    int b = i / EE, e = i % EE;
    int dst = edges[(long long)b * 2 * EE + EE + e];
    int pos = atomicAdd(&g_cur[b * 1026 + dst], 1);
    g_elist[b * EE + pos] = e;
}

// ============================ fused GNN attention ============================
__device__ __forceinline__ unsigned fenc(float f) {
    unsigned u = __float_as_uint(f);
    return (u & 0x80000000u) ? ~u : (u | 0x80000000u);
}
__device__ __forceinline__ float fdec(unsigned e) {
    return (e & 0x80000000u) ? __uint_as_float(e ^ 0x80000000u) : __uint_as_float(~e);
}

__global__ __launch_bounds__(256) void gnn_edge_kernel(
    const float* __restrict__ qkv,
    float* __restrict__ h,
    const int* __restrict__ edges, const int* __restrict__ etyp,
    const float* __restrict__ ET)
{
    const int node = blockIdx.x;
    const int b = blockIdx.y;
    const int tid = threadIdx.x;
    const int lane = tid & 31;
    const int w = tid >> 5;
    __shared__ float qs[256];
    __shared__ unsigned smax[4];
    __shared__ float sden[4];
    __shared__ float sagg[256];
    qs[tid] = qkv[((long long)b * 1025 + node) * 768 + tid];
    sagg[tid] = 0.f;
    if (tid < 4) { smax[tid] = 0u; sden[tid] = 0.f; }
    __syncthreads();
    const int off = g_off[b * 1026 + node];
    const int deg = g_off[b * 1026 + node + 1] - off;
    const int* el = g_elist + b * EE + off;
    const int* srcArr = edges + (long long)b * 2 * EE;

    float lmax[4] = { -1e30f, -1e30f, -1e30f, -1e30f };
    for (int ei = w; ei < deg; ei += 8) {
        int e = el[ei];
        int src = srcArr[e];
        int et = etyp[(long long)b * EE + e];
        const float* kr = qkv + ((long long)b * 1025 + src) * 768 + 256;
        const float* er = ET + et * 256;
        float hc[4] = {0.f, 0.f, 0.f, 0.f};
        #pragma unroll
        for (int i = 0; i < 8; i++) {
            int d = i * 32 + lane;
            hc[i >> 1] += qs[d] * (kr[d] + er[d]);
        }
        #pragma unroll
        for (int s = 16; s > 0; s >>= 1) {
            #pragma unroll
            for (int hh = 0; hh < 4; hh++) hc[hh] += __shfl_xor_sync(0xffffffffu, hc[hh], s);
        }
        #pragma unroll
        for (int hh = 0; hh < 4; hh++) {
            float lg = hc[hh] * 0.125f;
            lmax[hh] = fmaxf(lmax[hh], lg);
            hc[hh] = lg;
        }
        if (lane < 4) g_elog[((long long)b * EE + off + ei) * 4 + lane] = hc[lane];
    }
    if (lane == 0 && deg > 0) {
        #pragma unroll
        for (int hh = 0; hh < 4; hh++) atomicMax(&smax[hh], fenc(lmax[hh]));
    }
    __syncthreads();
    float mx[4];
    #pragma unroll
    for (int hh = 0; hh < 4; hh++) mx[hh] = fdec(smax[hh]);

    float vacc[8] = {0.f, 0.f, 0.f, 0.f, 0.f, 0.f, 0.f, 0.f};
    float wsum[4] = {0.f, 0.f, 0.f, 0.f};
    for (int ei = w; ei < deg; ei += 8) {
        int e = el[ei];
        int src = srcArr[e];
        float4 lg = *reinterpret_cast<const float4*>(&g_elog[((long long)b * EE + off + ei) * 4]);
        float ex[4];
        ex[0] = expf(lg.x - mx[0]);
        ex[1] = expf(lg.y - mx[1]);
        ex[2] = expf(lg.z - mx[2]);
        ex[3] = expf(lg.w - mx[3]);
        const float* vr = qkv + ((long long)b * 1025 + src) * 768 + 512;
        #pragma unroll
        for (int i = 0; i < 8; i++) {
            int d = i * 32 + lane;
            vacc[i] += ex[i >> 1] * vr[d];
        }
        if (lane == 0) {
            #pragma unroll
            for (int hh = 0; hh < 4; hh++) wsum[hh] += ex[hh];
        }
    }
    if (lane == 0 && deg > 0) {
        #pragma unroll
        for (int hh = 0; hh < 4; hh++) atomicAdd(&sden[hh], wsum[hh]);
    }
    #pragma unroll
    for (int i = 0; i < 8; i++) atomicAdd(&sagg[i * 32 + lane], vacc[i]);
    __syncthreads();
    float den = sden[tid >> 6] + 1e-9f;
    const long long rowOff = ((long long)b * 1025 + node) * 256;
    float val = fmaxf(h[rowOff + tid] + sagg[tid] / den, 0.f);
    h[rowOff + tid] = val;
    split_store(&g_HH[rowOff + tid], &g_HL[rowOff + tid], val);
}

// ============================ final classifier ============================
__global__ void out_kernel(float* __restrict__ out) {
    int c = blockIdx.x, b = blockIdx.y, t = threadIdx.x;
    __shared__ float red[256];
    const float* ctx = g_h + (long long)b * 1025 * 256;
    const float* lab = g_h + ((long long)b * 1025 + 1 + c) * 256;
    const float* txt = g_hin + b * 768;
    float s = 0.f;
    for (int kx = t; kx < 1280; kx += 256) {
        float x;
        if (kx < 256) x = ctx[kx];
        else if (kx < 512) x = lab[kx - 256];
        else x = txt[kx - 512];
        s += x * g_Wc[kx * 50 + c];
    }
    red[t] = s;
    __syncthreads();
    for (int st = 128; st > 0; st >>= 1) { if (t < st) red[t] += red[t + st]; __syncthreads(); }
    if (t == 0) out[b * 50 + c] = red[0] + g_bc[c];
}

// ============================ host ============================
static void launch_g(const __nv_bfloat16* Ah, const __nv_bfloat16* Al, long long sA,
                     const __nv_bfloat16* BH, const __nv_bfloat16* BL,
                     float* C, long long sC,
                     __nv_bfloat16* Ch, __nv_bfloat16* Cl, long long sCb,
                     int Mr, int Nc, int Kd,
                     const float* bias, const float* rowScale, long long sRS,
                     const float* addTab, const int* aidx, long long sAI, int relu) {
    dim3 grid(Nc / 128, (Mr + 127) / 128, BATCH);
    gemm_mma<0><<<grid, 256, GSMEM>>>(Ah, Al, sA, BH, BL, C, sC, Ch, Cl, sCb,
                                      Mr, Nc, Kd, bias, rowScale, sRS,
                                      addTab, aidx, sAI, relu, nullptr);
}

extern "C" void kernel_launch(void* const* d_in, const int* in_sizes, int n_in,
                              void* d_out, int out_size) {
    (void)in_sizes; (void)n_in; (void)out_size;
    const int*   sentence        = (const int*)d_in[0];
    const float* mask            = (const float*)d_in[1];
    const int*   nodes           = (const int*)d_in[2];
    const float* node_mask       = (const float*)d_in[3];
    const int*   node_types      = (const int*)d_in[4];
    const int*   edges           = (const int*)d_in[5];
    const int*   edge_types      = (const int*)d_in[6];
    const float* word_embed      = (const float*)d_in[7];
    const float* entity_table    = (const float*)d_in[8];
    const float* type_table      = (const float*)d_in[9];
    const float* mlp_w1          = (const float*)d_in[10];
    const float* mlp_b1          = (const float*)d_in[11];
    const float* mlp_w2          = (const float*)d_in[12];
    const float* mlp_b2          = (const float*)d_in[13];
    const float* ntw_w           = (const float*)d_in[14];
    const float* proj_w          = (const float*)d_in[15];
    const float* proj_b          = (const float*)d_in[16];
    const float* type_proj_w     = (const float*)d_in[17];
    const float* edge_type_table = (const float*)d_in[18];
    const float* gnn_wq          = (const float*)d_in[19];
    const float* gnn_wk          = (const float*)d_in[20];
    const float* gnn_wv          = (const float*)d_in[21];
    const float* gnn_we          = (const float*)d_in[22];
    const float* cls_w           = (const float*)d_in[23];
    const float* cls_b           = (const float*)d_in[24];
    const float* cls2_w          = (const float*)d_in[25];
    const float* cls2_b          = (const float*)d_in[26];
    float* out = (float*)d_out;

    cudaFuncSetAttribute(gemm_mma<0>, cudaFuncAttributeMaxDynamicSharedMemorySize, GSMEM);
    cudaFuncSetAttribute(gemm_mma<1>, cudaFuncAttributeMaxDynamicSharedMemorySize, GSMEM);

    float *pH, *pQKV, *pTpv, *pET, *pMsum;
    __nv_bfloat16 *pWH, *pWL, *pAH, *pAL, *pSH, *pSL, *pPH, *pPL, *pXH, *pXL, *pHH, *pHL;
    cudaGetSymbolAddress((void**)&pH, g_h);
    cudaGetSymbolAddress((void**)&pQKV, g_qkv);
    cudaGetSymbolAddress((void**)&pTpv, g_tpv);
    cudaGetSymbolAddress((void**)&pET, g_ET);
    cudaGetSymbolAddress((void**)&pMsum, g_msum);
    cudaGetSymbolAddress((void**)&pWH, g_WH);
    cudaGetSymbolAddress((void**)&pWL, g_WL);
    cudaGetSymbolAddress((void**)&pAH, g_AH);
    cudaGetSymbolAddress((void**)&pAL, g_AL);
    cudaGetSymbolAddress((void**)&pSH, g_SH);
    cudaGetSymbolAddress((void**)&pSL, g_SL);
    cudaGetSymbolAddress((void**)&pPH, g_PH);
    cudaGetSymbolAddress((void**)&pPL, g_PL);
    cudaGetSymbolAddress((void**)&pXH, g_XH);
    cudaGetSymbolAddress((void**)&pXL, g_XL);
    cudaGetSymbolAddress((void**)&pHH, g_HH);
    cudaGetSymbolAddress((void**)&pHL, g_HL);

    // fused small jobs
    mega_small<<<dim3(250, 7), 256>>>(sentence, mask, word_embed, type_table, type_proj_w,
                                      edge_type_table, gnn_we, cls_w, cls_b, cls2_w, cls2_b,
                                      node_mask);
    // weight splits
    P10 srcs;
    srcs.p[0] = mlp_w1; srcs.p[1] = mlp_w2; srcs.p[2] = ntw_w; srcs.p[3] = proj_w;
    srcs.p[4] = gnn_wq; srcs.p[5] = gnn_wk; srcs.p[6] = gnn_wv;
    srcs.p[7] = gnn_wq + 65536; srcs.p[8] = gnn_wk + 65536; srcs.p[9] = gnn_wv + 65536;
    mega_prep<<<dim3(3072, 10), 256>>>(srcs);
    // gather + split MLP1 A; kg pooling (split)
    gatherA<<<dim3(4096, 8), 256>>>(nodes, entity_table);
    poolkg_kernel<<<dim3(512, 8), 256>>>(nodes, node_mask, entity_table);
    // MLP1 fused -> S split
    {
        dim3 grid(1024 / 128, 4096 / 128, BATCH);
        gemm_mma<1><<<grid, 256, GSMEM>>>(pAH, pAL, 4096LL * 768,
                                          pWH + OFF_W1, pWL + OFF_W1,
                                          nullptr, 0, pSH, pSL, 512LL * 1024,
                                          4096, 1024, 768, mlp_b1, nullptr, 0,
                                          nullptr, nullptr, 0, 0, node_mask);
    }
    // MLP2: S @ W2 + b2*msum -> pooled[512:] split
    launch_g(pSH, pSL, 512LL * 1024, pWH + OFF_W2, pWL + OFF_W2,
             nullptr, 0, pPH + 512 * 768, pPL + 512 * 768, 1024LL * 768,
             512, 768, 1024, mlp_b2, pMsum + 512, 1024, nullptr, nullptr, 0, 0);
    // ntw: pooled @ ntw_w -> hin[1:] split
    launch_g(pPH, pPL, 1024LL * 768, pWH + OFF_NTW, pWL + OFF_NTW,
             nullptr, 0, pXH + 768, pXL + 768, 1025LL * 768,
             1024, 768, 768, nullptr, nullptr, 0, nullptr, nullptr, 0, 0);
    // proj: hin @ proj_w + proj_b + tpv[node_types] -> h fp32 + split
    launch_g(pXH, pXL, 1025LL * 768, pWH + OFF_PROJ, pWL + OFF_PROJ,
             pH, 1025LL * 256, pHH, pHL, 1025LL * 256,
             1025, 256, 768, proj_b, nullptr, 0, pTpv, node_types, 1025, 0);
    // CSR
    zero_cnt<<<(8 * 1026 + 255) / 256, 256>>>();
    count_kernel<<<(BATCH * EE) / 256, 256>>>(edges);
    scan_kernel<<<1, 8>>>();
    fill_kernel<<<(BATCH * EE) / 256, 256>>>(edges);
    // GNN layers
    for (int l = 0; l < 2; l++) {
        launch_g(pHH, pHL, 1025LL * 256,
                 pWH + OFF_QKV + l * 196608, pWL + OFF_QKV + l * 196608,
                 pQKV, 1025LL * 768, nullptr, nullptr, 0,
                 1025, 768, 256, nullptr, nullptr, 0, nullptr, nullptr, 0, 0);
        gnn_edge_kernel<<<dim3(1025, 8), 256>>>(pQKV, pH, edges, edge_types,
                                                pET + l * 50 * 256);
    }
    out_kernel<<<dim3(50, 8), 256>>>(out);
}